// round 15
// baseline (speedup 1.0000x reference)
#include <cuda_runtime.h>
#include <cuda_fp16.h>
#include <cstdint>

// Problem constants
#define BB 2
#define TT 2048
#define CC 1024
#define HH 16
#define DD 64
#define MM (BB*TT)   // 4096 rows

// Attention smem: 6 stages x 16KB (K 8KB | V 8KB), ssum after. Pair-processed.
#define STG_SZ   16384
#define OFF_SSUM 98304
#define ATTN_SMEM 98816

// GEMM smem: 3 stages x 32KB (Ah 16K | Bh 16K)
#define GSTG_SZ  32768
#define GEMM_SMEM (3 * GSTG_SZ)

// ---------------- scratch (no allocs allowed) ----------------
static __device__ __align__(128) __half g_xh[(size_t)MM * CC];
static __device__ __align__(128) __half g_w1h[(size_t)3 * CC * CC];
static __device__ __align__(128) __half g_w2h[(size_t)CC * CC];
static __device__ __align__(128) __half g_qkv[(size_t)MM * 3 * CC];
static __device__ __align__(128) __half g_ah[(size_t)MM * CC];

// ---------------- helpers ----------------
__device__ __forceinline__ uint32_t smem_u32(const void* p) {
    uint32_t a;
    asm("{ .reg .u64 t; cvta.to.shared.u64 t, %1; cvt.u32.u64 %0, t; }" : "=r"(a) : "l"(p));
    return a;
}

#define CPASYNC16(dst, src) \
    asm volatile("cp.async.cg.shared.global [%0], [%1], 16;" :: "r"(dst), "l"(src))
#define CP_COMMIT()  asm volatile("cp.async.commit_group;" ::: "memory")
#define CP_WAIT0()   asm volatile("cp.async.wait_group 0;" ::: "memory")
#define CP_WAIT1()   asm volatile("cp.async.wait_group 1;" ::: "memory")

#define LDSM4(r0, r1, r2, r3, addr) \
    asm volatile("ldmatrix.sync.aligned.m8n8.x4.shared.b16 {%0,%1,%2,%3}, [%4];" \
                 : "=r"(r0), "=r"(r1), "=r"(r2), "=r"(r3) : "r"(addr))

#define LDSM4T(r0, r1, r2, r3, addr) \
    asm volatile("ldmatrix.sync.aligned.m8n8.x4.trans.shared.b16 {%0,%1,%2,%3}, [%4];" \
                 : "=r"(r0), "=r"(r1), "=r"(r2), "=r"(r3) : "r"(addr))

#define MMA16816(d, a, b) \
    asm volatile("mma.sync.aligned.m16n8k16.row.col.f32.f16.f16.f32 " \
                 "{%0,%1,%2,%3}, {%4,%5,%6,%7}, {%8,%9}, {%0,%1,%2,%3};" \
                 : "+f"((d)[0]), "+f"((d)[1]), "+f"((d)[2]), "+f"((d)[3]) \
                 : "r"((a)[0]), "r"((a)[1]), "r"((a)[2]), "r"((a)[3]), \
                   "r"((b)[0]), "r"((b)[1]))

// streaming (evict-first) stores — attn_w / out are write-once streams
#define STG_CS_F2(ptr, x, y) \
    asm volatile("st.global.cs.v2.f32 [%0], {%1, %2};" :: "l"(ptr), "f"(x), "f"(y))
#define STG_CS_F4(ptr, x, y, z, w) \
    asm volatile("st.global.cs.v4.f32 [%0], {%1, %2, %3, %4};" \
                 :: "l"(ptr), "f"(x), "f"(y), "f"(z), "f"(w))

__device__ __forceinline__ uint32_t pack2h(float a, float b) {
    __half2 t;
    t.x = __float2half(a); t.y = __float2half(b);
    return *(uint32_t*)&t;
}

// ---------------------------------------------------------------------------
// prep kernels
// ---------------------------------------------------------------------------
__global__ void round_h8(const float4* __restrict__ in, uint4* __restrict__ hi, int n8) {
    int i = blockIdx.x * blockDim.x + threadIdx.x;
    if (i < n8) {
        float4 a = in[2 * i], b = in[2 * i + 1];
        hi[i] = make_uint4(pack2h(a.x, a.y), pack2h(a.z, a.w),
                           pack2h(b.x, b.y), pack2h(b.z, b.w));
    }
}

// w [K,N] f32 -> wT [N,K] fp16 (round)
__global__ void transpose_h(const float* __restrict__ w, __half* __restrict__ hi,
                            int K, int N) {
    __shared__ float t[32][33];
    int n0 = blockIdx.x * 32, k0 = blockIdx.y * 32;
    int tx = threadIdx.x, ty = threadIdx.y;
    #pragma unroll
    for (int j = 0; j < 32; j += 8)
        t[ty + j][tx] = w[(size_t)(k0 + ty + j) * N + n0 + tx];
    __syncthreads();
    #pragma unroll
    for (int j = 0; j < 32; j += 8)
        hi[(size_t)(n0 + ty + j) * K + k0 + tx] = __float2half(t[tx][ty + j]);
}

// ---------------------------------------------------------------------------
// fp16 single-pass GEMM: C[M,N] = Ah @ Bh^T + bias   (Bh as [N,K] fp16)
// 128x128 tile, BK=64, 3-stage cp.async pipeline, 2 CTAs/SM.
// ---------------------------------------------------------------------------
__global__ __launch_bounds__(256, 2) void mma_gemm(
    const __half* __restrict__ Ah, const __half* __restrict__ Bh,
    const float* __restrict__ bias,
    float* __restrict__ C, __half* __restrict__ Chi,
    int N, int K)
{
    extern __shared__ char smem[];
    const uint32_t sb = smem_u32(smem);
    const int tid = threadIdx.x;
    const int lane = tid & 31, wid = tid >> 5;
    const int warpM = wid >> 2, warpN = wid & 3;
    const int m0 = blockIdx.y * 128, n0 = blockIdx.x * 128;

    const __half* pAh = Ah + (size_t)m0 * K;
    const __half* pBh = Bh + (size_t)n0 * K;

    float acc[4][4][4] = {};
    const int nch = K >> 6;

    #define STAGE_LOAD(stg, kc) do {                                              \
        uint32_t s0_ = sb + (uint32_t)(stg) * GSTG_SZ;                            \
        _Pragma("unroll")                                                         \
        for (int i_ = 0; i_ < 4; i_++) {                                          \
            int idx_ = tid + i_ * 256;                                            \
            int row_ = idx_ >> 3, c16_ = idx_ & 7;                                \
            uint32_t so_ = (uint32_t)(row_ * 128 + ((c16_ ^ (row_ & 7)) << 4));   \
            size_t go_ = (size_t)row_ * K + (kc) + c16_ * 8;                      \
            CPASYNC16(s0_ + so_,          pAh + go_);                             \
            CPASYNC16(s0_ + 16384 + so_,  pBh + go_);                             \
        }                                                                         \
        CP_COMMIT();                                                              \
    } while (0)

    STAGE_LOAD(0, 0);
    if (nch > 1) STAGE_LOAD(1, 64);

    for (int c = 0; c < nch; c++) {
        if (c + 1 < nch) CP_WAIT1(); else CP_WAIT0();
        __syncthreads();
        if (c + 2 < nch) STAGE_LOAD((c + 2) % 3, (c + 2) * 64);

        const uint32_t aB = sb + (uint32_t)(c % 3) * GSTG_SZ;
        const uint32_t bB = aB + 16384;

        #pragma unroll
        for (int k16 = 0; k16 < 4; k16++) {
            uint32_t ah[4][4], bh[4][2];
            #pragma unroll
            for (int mi = 0; mi < 4; mi++) {
                int row = warpM * 64 + mi * 16 + (lane & 15);
                int c16 = k16 * 2 + (lane >> 4);
                uint32_t ad = aB + (uint32_t)(row * 128 + ((c16 ^ (row & 7)) << 4));
                LDSM4(ah[mi][0], ah[mi][1], ah[mi][2], ah[mi][3], ad);
            }
            #pragma unroll
            for (int p = 0; p < 2; p++) {
                int g = lane >> 3, r = lane & 7;
                int row = warpN * 32 + p * 16 + (g >> 1) * 8 + r;
                int c16 = k16 * 2 + (g & 1);
                uint32_t bd = bB + (uint32_t)(row * 128 + ((c16 ^ (row & 7)) << 4));
                uint32_t t0, t1, t2, t3;
                LDSM4(t0, t1, t2, t3, bd);
                bh[2*p][0] = t0; bh[2*p][1] = t1; bh[2*p+1][0] = t2; bh[2*p+1][1] = t3;
            }
            #pragma unroll
            for (int mi = 0; mi < 4; mi++)
                #pragma unroll
                for (int ni = 0; ni < 4; ni++)
                    MMA16816(acc[mi][ni], ah[mi], bh[ni]);
        }
        __syncthreads();
    }

    #pragma unroll
    for (int mi = 0; mi < 4; mi++) {
        int row = m0 + warpM * 64 + mi * 16 + (lane >> 2);
        #pragma unroll
        for (int ni = 0; ni < 4; ni++) {
            int col = n0 + warpN * 32 + ni * 8 + (lane & 3) * 2;
            float b0 = bias[col], b1 = bias[col + 1];
            float v00 = acc[mi][ni][0] + b0, v01 = acc[mi][ni][1] + b1;
            float v10 = acc[mi][ni][2] + b0, v11 = acc[mi][ni][3] + b1;
            if (Chi) {
                *(uint32_t*)&Chi[(size_t)row * N + col] = pack2h(v00, v01);
                *(uint32_t*)&Chi[(size_t)(row + 8) * N + col] = pack2h(v10, v11);
            } else {
                STG_CS_F2(&C[(size_t)row * N + col], v00, v01);
                STG_CS_F2(&C[(size_t)(row + 8) * N + col], v10, v11);
            }
        }
    }
    #undef STAGE_LOAD
}

// ---------------------------------------------------------------------------
// Two-pass flash attention, TQ=64, single-fp16 MMA, no running max.
// Tiles processed in PAIRS: 6-stage ring, one barrier + one commit per 2 tiles.
// ---------------------------------------------------------------------------
__global__ __launch_bounds__(256, 2) void attn_fa(
    const __half* __restrict__ qkv,
    float* __restrict__ attw, __half* __restrict__ oh)
{
    extern __shared__ char smem[];
    const uint32_t sb = smem_u32(smem);
    float* ssum = (float*)(smem + OFF_SSUM);
    const int tid = threadIdx.x, lane = tid & 31, wid = tid >> 5;
    const int rg = wid >> 1, cg = wid & 1;
    const int q0 = (int)(gridDim.x - 1 - blockIdx.x) * 64;   // big blocks first
    const int h  = blockIdx.y;
    const int b  = blockIdx.z;
    const int bT = b * TT;
    const int ntiles = (q0 >> 6) + 1;
    const int npairs = (ntiles + 1) >> 1;
    const int kspan  = ntiles * 64;
    const float scale = 0.125f;

    const int lr0 = rg * 16 + (lane >> 2);
    const int lr1 = lr0 + 8;
    const int qg0 = q0 + lr0, qg1 = q0 + lr1;

    #define ISSUE_H(tile, bufoff, colbase) do {                                     \
        _Pragma("unroll")                                                           \
        for (int i_ = 0; i_ < 2; i_++) {                                            \
            int idx_ = tid + i_ * 256;                                              \
            int rr_ = idx_ >> 3, cc_ = idx_ & 7;                                    \
            const __half* src_ = qkv +                                              \
                (size_t)(bT + (tile) * 64 + rr_) * 3072 + (colbase) + cc_ * 8;      \
            uint32_t dst_ = sb + (uint32_t)(bufoff) +                               \
                (uint32_t)(rr_ * 128 + ((cc_ ^ (rr_ & 7)) << 4));                   \
            CPASYNC16(dst_, src_);                                                  \
        }                                                                           \
    } while (0)

    // pair issue for pass A (K only): tiles 2p, 2p+1(if valid) -> stages (p%3)*2, +1
    #define ISSUE_PAIR_A(p) do {                                                    \
        int t0_ = 2 * (p);                                                          \
        uint32_t s0_ = (uint32_t)(((p) % 3) * 2) * STG_SZ;                          \
        ISSUE_H(t0_, s0_, CC + h * 64);                                             \
        if (t0_ + 1 < ntiles) ISSUE_H(t0_ + 1, s0_ + STG_SZ, CC + h * 64);          \
        CP_COMMIT();                                                                \
    } while (0)

    // pair issue for pass B (K + V)
    #define ISSUE_PAIR_B(p) do {                                                    \
        int t0_ = 2 * (p);                                                          \
        uint32_t s0_ = (uint32_t)(((p) % 3) * 2) * STG_SZ;                          \
        ISSUE_H(t0_, s0_, CC + h * 64);                                             \
        ISSUE_H(t0_, s0_ + 8192, 2 * CC + h * 64);                                  \
        if (t0_ + 1 < ntiles) {                                                     \
            ISSUE_H(t0_ + 1, s0_ + STG_SZ, CC + h * 64);                            \
            ISSUE_H(t0_ + 1, s0_ + STG_SZ + 8192, 2 * CC + h * 64);                 \
        }                                                                           \
        CP_COMMIT();                                                                \
    } while (0)

    #define COMPUTE_S(sa, kbuf) do {                                                \
        _Pragma("unroll")                                                           \
        for (int k32_ = 0; k32_ < 2; k32_++) {                                      \
            _Pragma("unroll")                                                       \
            for (int nt_ = 0; nt_ < 4; nt_++) {                                     \
                int rk_ = cg * 32 + nt_ * 8 + (lane & 7);                           \
                int c16_ = k32_ * 4 + (lane >> 3);                                  \
                uint32_t ad_ = (kbuf) + (uint32_t)(rk_ * 128 + ((c16_ ^ (rk_ & 7)) << 4)); \
                uint32_t kh_[4];                                                    \
                LDSM4(kh_[0], kh_[1], kh_[2], kh_[3], ad_);                         \
                uint32_t bh0_[2] = {kh_[0], kh_[1]}, bh1_[2] = {kh_[2], kh_[3]};    \
                MMA16816(sa[nt_], qfh[k32_*2],     bh0_);                           \
                MMA16816(sa[nt_], qfh[k32_*2 + 1], bh1_);                           \
            }                                                                       \
        }                                                                           \
    } while (0)

    // pass-A per-tile tail: accumulate l from sa
    #define ACC_L(sa, t) do {                                                       \
        _Pragma("unroll")                                                           \
        for (int nt = 0; nt < 4; nt++) {                                            \
            int j0 = (t) * 64 + cg * 32 + nt * 8 + (lane & 3) * 2;                  \
            l0 += __expf((j0     <= qg0) ? sa[nt][0] * scale : -1e30f);             \
            l0 += __expf((j0 + 1 <= qg0) ? sa[nt][1] * scale : -1e30f);             \
            l1 += __expf((j0     <= qg1) ? sa[nt][2] * scale : -1e30f);             \
            l1 += __expf((j0 + 1 <= qg1) ? sa[nt][3] * scale : -1e30f);             \
        }                                                                           \
    } while (0)

    // pass-B per-tile tail: p, attn_w, PV
    #define TILE_B(t, st) do {                                                      \
        float sa[4][4] = {};                                                        \
        COMPUTE_S(sa, sb + (st));                                                   \
        float p_[4][4];                                                             \
        _Pragma("unroll")                                                           \
        for (int nt = 0; nt < 4; nt++) {                                            \
            int j0 = (t) * 64 + cg * 32 + nt * 8 + (lane & 3) * 2;                  \
            p_[nt][0] = (j0     <= qg0) ? __expf(sa[nt][0] * scale) * invl0 : 0.f;  \
            p_[nt][1] = (j0 + 1 <= qg0) ? __expf(sa[nt][1] * scale) * invl0 : 0.f;  \
            p_[nt][2] = (j0     <= qg1) ? __expf(sa[nt][2] * scale) * invl1 : 0.f;  \
            p_[nt][3] = (j0 + 1 <= qg1) ? __expf(sa[nt][3] * scale) * invl1 : 0.f;  \
            if (wrow0) {                                                            \
                STG_CS_F2(wrow0 + j0, p_[nt][0], p_[nt][1]);                        \
                STG_CS_F2(wrow1 + j0, p_[nt][2], p_[nt][3]);                        \
            }                                                                       \
        }                                                                           \
        uint32_t pah[2][4];                                                         \
        _Pragma("unroll")                                                           \
        for (int kb = 0; kb < 2; kb++) {                                            \
            pah[kb][0] = pack2h(p_[2*kb][0],   p_[2*kb][1]);                        \
            pah[kb][1] = pack2h(p_[2*kb][2],   p_[2*kb][3]);                        \
            pah[kb][2] = pack2h(p_[2*kb+1][0], p_[2*kb+1][1]);                      \
            pah[kb][3] = pack2h(p_[2*kb+1][2], p_[2*kb+1][3]);                      \
        }                                                                           \
        const uint32_t vbuf_ = sb + (st) + 8192;                                    \
        _Pragma("unroll")                                                           \
        for (int nd = 0; nd < 8; nd++) {                                            \
            int rv = cg * 32 + (lane >> 3) * 8 + (lane & 7);                        \
            uint32_t ad = vbuf_ + (uint32_t)(rv * 128 + ((nd ^ (rv & 7)) << 4));    \
            uint32_t vh[4];                                                         \
            LDSM4T(vh[0], vh[1], vh[2], vh[3], ad);                                 \
            _Pragma("unroll")                                                       \
            for (int kb = 0; kb < 2; kb++) {                                        \
                uint32_t bvh[2] = {vh[kb*2], vh[kb*2+1]};                           \
                MMA16816(oa[nd], pah[kb], bvh);                                     \
            }                                                                       \
        }                                                                           \
    } while (0)

    // ---- Stage Q tile (hi only, 8KB) through stage 0; load fragments ----
    uint32_t qfh[4][4];
    {
        ISSUE_H(q0 >> 6, 0, h * 64);
        CP_COMMIT(); CP_WAIT0();
        __syncthreads();
        #pragma unroll
        for (int c = 0; c < 4; c++) {
            int row = rg * 16 + (lane & 15);
            int c16 = c * 2 + (lane >> 4);
            uint32_t ad = sb + (uint32_t)(row * 128 + ((c16 ^ (row & 7)) << 4));
            LDSM4(qfh[c][0], qfh[c][1], qfh[c][2], qfh[c][3], ad);
        }
        __syncthreads();
    }

    // ---- zero tail of attn_w (streaming) ----
    if (attw && kspan < TT) {
        const int ntail4 = (TT - kspan) >> 2;
        float* wb = attw + ((size_t)(b * HH + h) * TT + q0) * TT;
        for (int i = tid; i < 64 * ntail4; i += 256) {
            int r = i / ntail4, c = i - r * ntail4;
            STG_CS_F4(wb + (size_t)r * TT + kspan + c * 4, 0.f, 0.f, 0.f, 0.f);
        }
    }

    // ---- Pass A: l = sum exp(s), K tiles only, pair-processed ----
    float l0 = 0.f, l1 = 0.f;

    ISSUE_PAIR_A(0);
    if (npairs > 1) ISSUE_PAIR_A(1);
    for (int p = 0; p < npairs; p++) {
        if (p + 1 < npairs) CP_WAIT1(); else CP_WAIT0();
        __syncthreads();
        if (p + 2 < npairs) ISSUE_PAIR_A(p + 2);

        const uint32_t s0 = (uint32_t)((p % 3) * 2) * STG_SZ;
        {
            float sa[4][4] = {};
            COMPUTE_S(sa, sb + s0);
            ACC_L(sa, 2 * p);
        }
        if (2 * p + 1 < ntiles) {
            float sa[4][4] = {};
            COMPUTE_S(sa, sb + s0 + STG_SZ);
            ACC_L(sa, 2 * p + 1);
        }
    }
    l0 += __shfl_xor_sync(0xffffffffu, l0, 1);
    l0 += __shfl_xor_sync(0xffffffffu, l0, 2);
    l1 += __shfl_xor_sync(0xffffffffu, l1, 1);
    l1 += __shfl_xor_sync(0xffffffffu, l1, 2);
    __syncthreads();
    if ((lane & 3) == 0) { ssum[cg * 64 + lr0] = l0; ssum[cg * 64 + lr1] = l1; }
    __syncthreads();
    const float invl0 = 1.0f / (ssum[lr0] + ssum[64 + lr0]);
    const float invl1 = 1.0f / (ssum[lr1] + ssum[64 + lr1]);

    // ---- Pass B: recompute S, emit attn_w, PV, pair-processed ----
    float oa[8][4] = {};
    float* wrow0 = attw ? attw + (((size_t)(b * HH + h) * TT + qg0) * TT) : (float*)0;
    float* wrow1 = attw ? attw + (((size_t)(b * HH + h) * TT + qg1) * TT) : (float*)0;

    ISSUE_PAIR_B(0);
    if (npairs > 1) ISSUE_PAIR_B(1);
    for (int p = 0; p < npairs; p++) {
        if (p + 1 < npairs) CP_WAIT1(); else CP_WAIT0();
        __syncthreads();
        if (p + 2 < npairs) ISSUE_PAIR_B(p + 2);

        const uint32_t s0 = (uint32_t)((p % 3) * 2) * STG_SZ;
        TILE_B(2 * p, s0);
        if (2 * p + 1 < ntiles) TILE_B(2 * p + 1, s0 + STG_SZ);
    }
    __syncthreads();

    // ---- reduce col-group pairs, emit fp16 ----
    float* ored = (float*)smem;   // 64 x 64 fp32 (reuses stages)
    if (cg == 1) {
        #pragma unroll
        for (int nd = 0; nd < 8; nd++) {
            int d0 = nd * 8 + (lane & 3) * 2;
            *(float2*)&ored[lr0 * 64 + d0] = make_float2(oa[nd][0], oa[nd][1]);
            *(float2*)&ored[lr1 * 64 + d0] = make_float2(oa[nd][2], oa[nd][3]);
        }
    }
    __syncthreads();
    if (cg == 0) {
        #pragma unroll
        for (int nd = 0; nd < 8; nd++) {
            int d0 = nd * 8 + (lane & 3) * 2;
            float2 q0v = *(float2*)&ored[lr0 * 64 + d0];
            float2 q1v = *(float2*)&ored[lr1 * 64 + d0];
            size_t r1 = (size_t)(bT + qg0) * CC + h * 64 + d0;
            size_t r2 = (size_t)(bT + qg1) * CC + h * 64 + d0;
            *(uint32_t*)&oh[r1] = pack2h(oa[nd][0] + q0v.x, oa[nd][1] + q0v.y);
            *(uint32_t*)&oh[r2] = pack2h(oa[nd][2] + q1v.x, oa[nd][3] + q1v.y);
        }
    }
    #undef ISSUE_H
    #undef ISSUE_PAIR_A
    #undef ISSUE_PAIR_B
    #undef COMPUTE_S
    #undef ACC_L
    #undef TILE_B
}

// ---------------------------------------------------------------------------
extern "C" void kernel_launch(void* const* d_in, const int* in_sizes, int n_in,
                              void* d_out, int out_size)
{
    (void)in_sizes; (void)n_in;
    const float* x     = (const float*)d_in[0];
    const float* w_qkv = (const float*)d_in[1];
    const float* b_qkv = (const float*)d_in[2];
    const float* w_o   = (const float*)d_in[3];
    const float* b_o   = (const float*)d_in[4];
    float* out = (float*)d_out;

    __half *xh, *w1h, *w2h, *qkv, *ah;
    cudaGetSymbolAddress((void**)&xh, g_xh);
    cudaGetSymbolAddress((void**)&w1h, g_w1h); cudaGetSymbolAddress((void**)&w2h, g_w2h);
    cudaGetSymbolAddress((void**)&qkv, g_qkv); cudaGetSymbolAddress((void**)&ah, g_ah);

    cudaFuncSetAttribute(mma_gemm, cudaFuncAttributeMaxDynamicSharedMemorySize, GEMM_SMEM);
    cudaFuncSetAttribute(attn_fa, cudaFuncAttributeMaxDynamicSharedMemorySize, ATTN_SMEM);

    // prep
    round_h8<<<(MM * CC / 8 + 255) / 256, 256>>>((const float4*)x, (uint4*)xh, MM * CC / 8);
    transpose_h<<<dim3(3 * CC / 32, CC / 32), dim3(32, 8)>>>(w_qkv, w1h, CC, 3 * CC);
    transpose_h<<<dim3(CC / 32, CC / 32), dim3(32, 8)>>>(w_o, w2h, CC, CC);

    // 1) QKV projection -> fp16
    mma_gemm<<<dim3(3 * CC / 128, MM / 128), 256, GEMM_SMEM>>>(
        xh, w1h, b_qkv, (float*)0, qkv, 3 * CC, CC);

    // 2) attention (two-pass flash, TQ=64, pair-processed)
    size_t o_elems = (size_t)MM * CC;
    float* attw = ((size_t)out_size > o_elems) ? out + o_elems : (float*)0;
    dim3 g2(TT / 64, HH, BB);
    attn_fa<<<g2, 256, ATTN_SMEM>>>(qkv, attw, ah);

    // 3) output projection (fp32 out, streaming)
    mma_gemm<<<dim3(CC / 128, MM / 128), 256, GEMM_SMEM>>>(
        ah, w2h, b_o, out, (__half*)0, CC, CC);
}

// round 16
// speedup vs baseline: 1.0407x; 1.0407x over previous
#include <cuda_runtime.h>
#include <cuda_fp16.h>
#include <cstdint>

// Problem constants
#define BB 2
#define TT 2048
#define CC 1024
#define HH 16
#define DD 64
#define MM (BB*TT)   // 4096 rows

// Attention smem: 6 stages x 16KB (K 8KB | V 8KB), ssum after. Pair-processed.
#define STG_SZ   16384
#define OFF_SSUM 98304
#define ATTN_SMEM 98816

// GEMM smem: 3 stages x 32KB (Ah 16K | Bh 16K)
#define GSTG_SZ  32768
#define GEMM_SMEM (3 * GSTG_SZ)

// ---------------- scratch (no allocs allowed) ----------------
static __device__ __align__(128) __half g_xh[(size_t)MM * CC];
static __device__ __align__(128) __half g_w1h[(size_t)3 * CC * CC];
static __device__ __align__(128) __half g_w2h[(size_t)CC * CC];
static __device__ __align__(128) __half g_qkv[(size_t)MM * 3 * CC];
static __device__ __align__(128) __half g_ah[(size_t)MM * CC];
static __device__ __align__(128) float  g_b1[3 * CC];

// ---------------- helpers ----------------
__device__ __forceinline__ uint32_t smem_u32(const void* p) {
    uint32_t a;
    asm("{ .reg .u64 t; cvta.to.shared.u64 t, %1; cvt.u32.u64 %0, t; }" : "=r"(a) : "l"(p));
    return a;
}

#define CPASYNC16(dst, src) \
    asm volatile("cp.async.cg.shared.global [%0], [%1], 16;" :: "r"(dst), "l"(src))
#define CP_COMMIT()  asm volatile("cp.async.commit_group;" ::: "memory")
#define CP_WAIT0()   asm volatile("cp.async.wait_group 0;" ::: "memory")
#define CP_WAIT1()   asm volatile("cp.async.wait_group 1;" ::: "memory")

#define LDSM4(r0, r1, r2, r3, addr) \
    asm volatile("ldmatrix.sync.aligned.m8n8.x4.shared.b16 {%0,%1,%2,%3}, [%4];" \
                 : "=r"(r0), "=r"(r1), "=r"(r2), "=r"(r3) : "r"(addr))

#define LDSM4T(r0, r1, r2, r3, addr) \
    asm volatile("ldmatrix.sync.aligned.m8n8.x4.trans.shared.b16 {%0,%1,%2,%3}, [%4];" \
                 : "=r"(r0), "=r"(r1), "=r"(r2), "=r"(r3) : "r"(addr))

#define MMA16816(d, a, b) \
    asm volatile("mma.sync.aligned.m16n8k16.row.col.f32.f16.f16.f32 " \
                 "{%0,%1,%2,%3}, {%4,%5,%6,%7}, {%8,%9}, {%0,%1,%2,%3};" \
                 : "+f"((d)[0]), "+f"((d)[1]), "+f"((d)[2]), "+f"((d)[3]) \
                 : "r"((a)[0]), "r"((a)[1]), "r"((a)[2]), "r"((a)[3]), \
                   "r"((b)[0]), "r"((b)[1]))

// streaming (evict-first) stores — attn_w / out are write-once streams
#define STG_CS_F2(ptr, x, y) \
    asm volatile("st.global.cs.v2.f32 [%0], {%1, %2};" :: "l"(ptr), "f"(x), "f"(y))
#define STG_CS_F4(ptr, x, y, z, w) \
    asm volatile("st.global.cs.v4.f32 [%0], {%1, %2, %3, %4};" \
                 :: "l"(ptr), "f"(x), "f"(y), "f"(z), "f"(w))

__device__ __forceinline__ uint32_t pack2h(float a, float b) {
    __half2 t;
    t.x = __float2half(a); t.y = __float2half(b);
    return *(uint32_t*)&t;
}

// ---------------------------------------------------------------------------
// prep kernels
// ---------------------------------------------------------------------------
__global__ void round_h8(const float4* __restrict__ in, uint4* __restrict__ hi, int n8) {
    int i = blockIdx.x * blockDim.x + threadIdx.x;
    if (i < n8) {
        float4 a = in[2 * i], b = in[2 * i + 1];
        hi[i] = make_uint4(pack2h(a.x, a.y), pack2h(a.z, a.w),
                           pack2h(b.x, b.y), pack2h(b.z, b.w));
    }
}

// bias copy with Q-columns pre-scaled by 1/8 (exact power of 2)
__global__ void scale_bias(const float* __restrict__ in, float* __restrict__ out, int n) {
    int i = blockIdx.x * blockDim.x + threadIdx.x;
    if (i < n) out[i] = in[i] * ((i < CC) ? 0.125f : 1.0f);
}

// w [K,N] f32 -> wT [N,K] fp16; columns n < sc_cols scaled by 1/8 (exact)
__global__ void transpose_h(const float* __restrict__ w, __half* __restrict__ hi,
                            int K, int N, int sc_cols) {
    __shared__ float t[32][33];
    int n0 = blockIdx.x * 32, k0 = blockIdx.y * 32;
    int tx = threadIdx.x, ty = threadIdx.y;
    #pragma unroll
    for (int j = 0; j < 32; j += 8)
        t[ty + j][tx] = w[(size_t)(k0 + ty + j) * N + n0 + tx];
    __syncthreads();
    #pragma unroll
    for (int j = 0; j < 32; j += 8) {
        int n = n0 + ty + j;
        float v = t[tx][ty + j];
        if (n < sc_cols) v *= 0.125f;
        hi[(size_t)n * K + k0 + tx] = __float2half(v);
    }
}

// ---------------------------------------------------------------------------
// fp16 single-pass GEMM: C[M,N] = Ah @ Bh^T + bias   (Bh as [N,K] fp16)
// 128x128 tile, BK=64, 3-stage cp.async pipeline, 2 CTAs/SM.
// ---------------------------------------------------------------------------
__global__ __launch_bounds__(256, 2) void mma_gemm(
    const __half* __restrict__ Ah, const __half* __restrict__ Bh,
    const float* __restrict__ bias,
    float* __restrict__ C, __half* __restrict__ Chi,
    int N, int K)
{
    extern __shared__ char smem[];
    const uint32_t sb = smem_u32(smem);
    const int tid = threadIdx.x;
    const int lane = tid & 31, wid = tid >> 5;
    const int warpM = wid >> 2, warpN = wid & 3;
    const int m0 = blockIdx.y * 128, n0 = blockIdx.x * 128;

    const __half* pAh = Ah + (size_t)m0 * K;
    const __half* pBh = Bh + (size_t)n0 * K;

    float acc[4][4][4] = {};
    const int nch = K >> 6;

    #define STAGE_LOAD(stg, kc) do {                                              \
        uint32_t s0_ = sb + (uint32_t)(stg) * GSTG_SZ;                            \
        _Pragma("unroll")                                                         \
        for (int i_ = 0; i_ < 4; i_++) {                                          \
            int idx_ = tid + i_ * 256;                                            \
            int row_ = idx_ >> 3, c16_ = idx_ & 7;                                \
            uint32_t so_ = (uint32_t)(row_ * 128 + ((c16_ ^ (row_ & 7)) << 4));   \
            size_t go_ = (size_t)row_ * K + (kc) + c16_ * 8;                      \
            CPASYNC16(s0_ + so_,          pAh + go_);                             \
            CPASYNC16(s0_ + 16384 + so_,  pBh + go_);                             \
        }                                                                         \
        CP_COMMIT();                                                              \
    } while (0)

    STAGE_LOAD(0, 0);
    if (nch > 1) STAGE_LOAD(1, 64);

    for (int c = 0; c < nch; c++) {
        if (c + 1 < nch) CP_WAIT1(); else CP_WAIT0();
        __syncthreads();
        if (c + 2 < nch) STAGE_LOAD((c + 2) % 3, (c + 2) * 64);

        const uint32_t aB = sb + (uint32_t)(c % 3) * GSTG_SZ;
        const uint32_t bB = aB + 16384;

        #pragma unroll
        for (int k16 = 0; k16 < 4; k16++) {
            uint32_t ah[4][4], bh[4][2];
            #pragma unroll
            for (int mi = 0; mi < 4; mi++) {
                int row = warpM * 64 + mi * 16 + (lane & 15);
                int c16 = k16 * 2 + (lane >> 4);
                uint32_t ad = aB + (uint32_t)(row * 128 + ((c16 ^ (row & 7)) << 4));
                LDSM4(ah[mi][0], ah[mi][1], ah[mi][2], ah[mi][3], ad);
            }
            #pragma unroll
            for (int p = 0; p < 2; p++) {
                int g = lane >> 3, r = lane & 7;
                int row = warpN * 32 + p * 16 + (g >> 1) * 8 + r;
                int c16 = k16 * 2 + (g & 1);
                uint32_t bd = bB + (uint32_t)(row * 128 + ((c16 ^ (row & 7)) << 4));
                uint32_t t0, t1, t2, t3;
                LDSM4(t0, t1, t2, t3, bd);
                bh[2*p][0] = t0; bh[2*p][1] = t1; bh[2*p+1][0] = t2; bh[2*p+1][1] = t3;
            }
            #pragma unroll
            for (int mi = 0; mi < 4; mi++)
                #pragma unroll
                for (int ni = 0; ni < 4; ni++)
                    MMA16816(acc[mi][ni], ah[mi], bh[ni]);
        }
        __syncthreads();
    }

    #pragma unroll
    for (int mi = 0; mi < 4; mi++) {
        int row = m0 + warpM * 64 + mi * 16 + (lane >> 2);
        #pragma unroll
        for (int ni = 0; ni < 4; ni++) {
            int col = n0 + warpN * 32 + ni * 8 + (lane & 3) * 2;
            float b0 = bias[col], b1 = bias[col + 1];
            float v00 = acc[mi][ni][0] + b0, v01 = acc[mi][ni][1] + b1;
            float v10 = acc[mi][ni][2] + b0, v11 = acc[mi][ni][3] + b1;
            if (Chi) {
                *(uint32_t*)&Chi[(size_t)row * N + col] = pack2h(v00, v01);
                *(uint32_t*)&Chi[(size_t)(row + 8) * N + col] = pack2h(v10, v11);
            } else {
                STG_CS_F2(&C[(size_t)row * N + col], v00, v01);
                STG_CS_F2(&C[(size_t)(row + 8) * N + col], v10, v11);
            }
        }
    }
    #undef STAGE_LOAD
}

// ---------------------------------------------------------------------------
// Two-pass flash attention, TQ=64, single-fp16 MMA, no running max.
// Q pre-scaled by 1/8 upstream (exact). Masking only on the diagonal tile.
// Pair-processed 6-stage ring.
// ---------------------------------------------------------------------------
__global__ __launch_bounds__(256, 2) void attn_fa(
    const __half* __restrict__ qkv,
    float* __restrict__ attw, __half* __restrict__ oh)
{
    extern __shared__ char smem[];
    const uint32_t sb = smem_u32(smem);
    float* ssum = (float*)(smem + OFF_SSUM);
    const int tid = threadIdx.x, lane = tid & 31, wid = tid >> 5;
    const int rg = wid >> 1, cg = wid & 1;
    const int q0 = (int)(gridDim.x - 1 - blockIdx.x) * 64;   // big blocks first
    const int h  = blockIdx.y;
    const int b  = blockIdx.z;
    const int bT = b * TT;
    const int ntiles = (q0 >> 6) + 1;
    const int npairs = (ntiles + 1) >> 1;
    const int kspan  = ntiles * 64;

    const int lr0 = rg * 16 + (lane >> 2);
    const int lr1 = lr0 + 8;
    const int qg0 = q0 + lr0, qg1 = q0 + lr1;

    #define ISSUE_H(tile, bufoff, colbase) do {                                     \
        _Pragma("unroll")                                                           \
        for (int i_ = 0; i_ < 2; i_++) {                                            \
            int idx_ = tid + i_ * 256;                                              \
            int rr_ = idx_ >> 3, cc_ = idx_ & 7;                                    \
            const __half* src_ = qkv +                                              \
                (size_t)(bT + (tile) * 64 + rr_) * 3072 + (colbase) + cc_ * 8;      \
            uint32_t dst_ = sb + (uint32_t)(bufoff) +                               \
                (uint32_t)(rr_ * 128 + ((cc_ ^ (rr_ & 7)) << 4));                   \
            CPASYNC16(dst_, src_);                                                  \
        }                                                                           \
    } while (0)

    #define ISSUE_PAIR_A(p) do {                                                    \
        int t0_ = 2 * (p);                                                          \
        uint32_t s0_ = (uint32_t)(((p) % 3) * 2) * STG_SZ;                          \
        ISSUE_H(t0_, s0_, CC + h * 64);                                             \
        if (t0_ + 1 < ntiles) ISSUE_H(t0_ + 1, s0_ + STG_SZ, CC + h * 64);          \
        CP_COMMIT();                                                                \
    } while (0)

    #define ISSUE_PAIR_B(p) do {                                                    \
        int t0_ = 2 * (p);                                                          \
        uint32_t s0_ = (uint32_t)(((p) % 3) * 2) * STG_SZ;                          \
        ISSUE_H(t0_, s0_, CC + h * 64);                                             \
        ISSUE_H(t0_, s0_ + 8192, 2 * CC + h * 64);                                  \
        if (t0_ + 1 < ntiles) {                                                     \
            ISSUE_H(t0_ + 1, s0_ + STG_SZ, CC + h * 64);                            \
            ISSUE_H(t0_ + 1, s0_ + STG_SZ + 8192, 2 * CC + h * 64);                 \
        }                                                                           \
        CP_COMMIT();                                                                \
    } while (0)

    #define COMPUTE_S(sa, kbuf) do {                                                \
        _Pragma("unroll")                                                           \
        for (int k32_ = 0; k32_ < 2; k32_++) {                                      \
            _Pragma("unroll")                                                       \
            for (int nt_ = 0; nt_ < 4; nt_++) {                                     \
                int rk_ = cg * 32 + nt_ * 8 + (lane & 7);                           \
                int c16_ = k32_ * 4 + (lane >> 3);                                  \
                uint32_t ad_ = (kbuf) + (uint32_t)(rk_ * 128 + ((c16_ ^ (rk_ & 7)) << 4)); \
                uint32_t kh_[4];                                                    \
                LDSM4(kh_[0], kh_[1], kh_[2], kh_[3], ad_);                         \
                uint32_t bh0_[2] = {kh_[0], kh_[1]}, bh1_[2] = {kh_[2], kh_[3]};    \
                MMA16816(sa[nt_], qfh[k32_*2],     bh0_);                           \
                MMA16816(sa[nt_], qfh[k32_*2 + 1], bh1_);                           \
            }                                                                       \
        }                                                                           \
    } while (0)

    // pass-A per-tile tail: accumulate l (msk: apply causal mask — last tile only)
    #define ACC_L(sa, t, msk) do {                                                  \
        if (msk) {                                                                  \
            _Pragma("unroll")                                                       \
            for (int nt = 0; nt < 4; nt++) {                                        \
                int j0 = (t) * 64 + cg * 32 + nt * 8 + (lane & 3) * 2;              \
                l0 += (j0     <= qg0) ? __expf(sa[nt][0]) : 0.f;                    \
                l0 += (j0 + 1 <= qg0) ? __expf(sa[nt][1]) : 0.f;                    \
                l1 += (j0     <= qg1) ? __expf(sa[nt][2]) : 0.f;                    \
                l1 += (j0 + 1 <= qg1) ? __expf(sa[nt][3]) : 0.f;                    \
            }                                                                       \
        } else {                                                                    \
            _Pragma("unroll")                                                       \
            for (int nt = 0; nt < 4; nt++) {                                        \
                l0 += __expf(sa[nt][0]); l0 += __expf(sa[nt][1]);                   \
                l1 += __expf(sa[nt][2]); l1 += __expf(sa[nt][3]);                   \
            }                                                                       \
        }                                                                           \
    } while (0)

    // pass-B per-tile tail: p, attn_w, PV (msk only on last tile)
    #define TILE_B(t, st, msk) do {                                                 \
        float sa[4][4] = {};                                                        \
        COMPUTE_S(sa, sb + (st));                                                   \
        float p_[4][4];                                                             \
        _Pragma("unroll")                                                           \
        for (int nt = 0; nt < 4; nt++) {                                            \
            int j0 = (t) * 64 + cg * 32 + nt * 8 + (lane & 3) * 2;                  \
            if (msk) {                                                              \
                p_[nt][0] = (j0     <= qg0) ? __expf(sa[nt][0]) * invl0 : 0.f;      \
                p_[nt][1] = (j0 + 1 <= qg0) ? __expf(sa[nt][1]) * invl0 : 0.f;      \
                p_[nt][2] = (j0     <= qg1) ? __expf(sa[nt][2]) * invl1 : 0.f;      \
                p_[nt][3] = (j0 + 1 <= qg1) ? __expf(sa[nt][3]) * invl1 : 0.f;      \
            } else {                                                                \
                p_[nt][0] = __expf(sa[nt][0]) * invl0;                              \
                p_[nt][1] = __expf(sa[nt][1]) * invl0;                              \
                p_[nt][2] = __expf(sa[nt][2]) * invl1;                              \
                p_[nt][3] = __expf(sa[nt][3]) * invl1;                              \
            }                                                                       \
            if (wrow0) {                                                            \
                STG_CS_F2(wrow0 + j0, p_[nt][0], p_[nt][1]);                        \
                STG_CS_F2(wrow1 + j0, p_[nt][2], p_[nt][3]);                        \
            }                                                                       \
        }                                                                           \
        uint32_t pah[2][4];                                                         \
        _Pragma("unroll")                                                           \
        for (int kb = 0; kb < 2; kb++) {                                            \
            pah[kb][0] = pack2h(p_[2*kb][0],   p_[2*kb][1]);                        \
            pah[kb][1] = pack2h(p_[2*kb][2],   p_[2*kb][3]);                        \
            pah[kb][2] = pack2h(p_[2*kb+1][0], p_[2*kb+1][1]);                      \
            pah[kb][3] = pack2h(p_[2*kb+1][2], p_[2*kb+1][3]);                      \
        }                                                                           \
        const uint32_t vbuf_ = sb + (st) + 8192;                                    \
        _Pragma("unroll")                                                           \
        for (int nd = 0; nd < 8; nd++) {                                            \
            int rv = cg * 32 + (lane >> 3) * 8 + (lane & 7);                        \
            uint32_t ad = vbuf_ + (uint32_t)(rv * 128 + ((nd ^ (rv & 7)) << 4));    \
            uint32_t vh[4];                                                         \
            LDSM4T(vh[0], vh[1], vh[2], vh[3], ad);                                 \
            _Pragma("unroll")                                                       \
            for (int kb = 0; kb < 2; kb++) {                                        \
                uint32_t bvh[2] = {vh[kb*2], vh[kb*2+1]};                           \
                MMA16816(oa[nd], pah[kb], bvh);                                     \
            }                                                                       \
        }                                                                           \
    } while (0)

    // ---- Stage Q tile (hi only, 8KB) through stage 0; load fragments ----
    uint32_t qfh[4][4];
    {
        ISSUE_H(q0 >> 6, 0, h * 64);
        CP_COMMIT(); CP_WAIT0();
        __syncthreads();
        #pragma unroll
        for (int c = 0; c < 4; c++) {
            int row = rg * 16 + (lane & 15);
            int c16 = c * 2 + (lane >> 4);
            uint32_t ad = sb + (uint32_t)(row * 128 + ((c16 ^ (row & 7)) << 4));
            LDSM4(qfh[c][0], qfh[c][1], qfh[c][2], qfh[c][3], ad);
        }
        __syncthreads();
    }

    // ---- zero tail of attn_w (streaming) ----
    if (attw && kspan < TT) {
        const int ntail4 = (TT - kspan) >> 2;
        float* wb = attw + ((size_t)(b * HH + h) * TT + q0) * TT;
        for (int i = tid; i < 64 * ntail4; i += 256) {
            int r = i / ntail4, c = i - r * ntail4;
            STG_CS_F4(wb + (size_t)r * TT + kspan + c * 4, 0.f, 0.f, 0.f, 0.f);
        }
    }

    // ---- Pass A: l = sum exp(s), K tiles only, pair-processed ----
    float l0 = 0.f, l1 = 0.f;

    ISSUE_PAIR_A(0);
    if (npairs > 1) ISSUE_PAIR_A(1);
    for (int p = 0; p < npairs; p++) {
        if (p + 1 < npairs) CP_WAIT1(); else CP_WAIT0();
        __syncthreads();
        if (p + 2 < npairs) ISSUE_PAIR_A(p + 2);

        const uint32_t s0 = (uint32_t)((p % 3) * 2) * STG_SZ;
        {
            float sa[4][4] = {};
            COMPUTE_S(sa, sb + s0);
            ACC_L(sa, 2 * p, (2 * p == ntiles - 1));
        }
        if (2 * p + 1 < ntiles) {
            float sa[4][4] = {};
            COMPUTE_S(sa, sb + s0 + STG_SZ);
            ACC_L(sa, 2 * p + 1, (2 * p + 1 == ntiles - 1));
        }
    }
    l0 += __shfl_xor_sync(0xffffffffu, l0, 1);
    l0 += __shfl_xor_sync(0xffffffffu, l0, 2);
    l1 += __shfl_xor_sync(0xffffffffu, l1, 1);
    l1 += __shfl_xor_sync(0xffffffffu, l1, 2);
    __syncthreads();
    if ((lane & 3) == 0) { ssum[cg * 64 + lr0] = l0; ssum[cg * 64 + lr1] = l1; }
    __syncthreads();
    const float invl0 = 1.0f / (ssum[lr0] + ssum[64 + lr0]);
    const float invl1 = 1.0f / (ssum[lr1] + ssum[64 + lr1]);

    // ---- Pass B: recompute S, emit attn_w, PV, pair-processed ----
    float oa[8][4] = {};
    float* wrow0 = attw ? attw + (((size_t)(b * HH + h) * TT + qg0) * TT) : (float*)0;
    float* wrow1 = attw ? attw + (((size_t)(b * HH + h) * TT + qg1) * TT) : (float*)0;

    ISSUE_PAIR_B(0);
    if (npairs > 1) ISSUE_PAIR_B(1);
    for (int p = 0; p < npairs; p++) {
        if (p + 1 < npairs) CP_WAIT1(); else CP_WAIT0();
        __syncthreads();
        if (p + 2 < npairs) ISSUE_PAIR_B(p + 2);

        const uint32_t s0 = (uint32_t)((p % 3) * 2) * STG_SZ;
        TILE_B(2 * p, s0, (2 * p == ntiles - 1));
        if (2 * p + 1 < ntiles) TILE_B(2 * p + 1, s0 + STG_SZ, (2 * p + 1 == ntiles - 1));
    }
    __syncthreads();

    // ---- reduce col-group pairs, emit fp16 ----
    float* ored = (float*)smem;   // 64 x 64 fp32 (reuses stages)
    if (cg == 1) {
        #pragma unroll
        for (int nd = 0; nd < 8; nd++) {
            int d0 = nd * 8 + (lane & 3) * 2;
            *(float2*)&ored[lr0 * 64 + d0] = make_float2(oa[nd][0], oa[nd][1]);
            *(float2*)&ored[lr1 * 64 + d0] = make_float2(oa[nd][2], oa[nd][3]);
        }
    }
    __syncthreads();
    if (cg == 0) {
        #pragma unroll
        for (int nd = 0; nd < 8; nd++) {
            int d0 = nd * 8 + (lane & 3) * 2;
            float2 q0v = *(float2*)&ored[lr0 * 64 + d0];
            float2 q1v = *(float2*)&ored[lr1 * 64 + d0];
            size_t r1 = (size_t)(bT + qg0) * CC + h * 64 + d0;
            size_t r2 = (size_t)(bT + qg1) * CC + h * 64 + d0;
            *(uint32_t*)&oh[r1] = pack2h(oa[nd][0] + q0v.x, oa[nd][1] + q0v.y);
            *(uint32_t*)&oh[r2] = pack2h(oa[nd][2] + q1v.x, oa[nd][3] + q1v.y);
        }
    }
    #undef ISSUE_H
    #undef ISSUE_PAIR_A
    #undef ISSUE_PAIR_B
    #undef COMPUTE_S
    #undef ACC_L
    #undef TILE_B
}

// ---------------------------------------------------------------------------
extern "C" void kernel_launch(void* const* d_in, const int* in_sizes, int n_in,
                              void* d_out, int out_size)
{
    (void)in_sizes; (void)n_in;
    const float* x     = (const float*)d_in[0];
    const float* w_qkv = (const float*)d_in[1];
    const float* b_qkv = (const float*)d_in[2];
    const float* w_o   = (const float*)d_in[3];
    const float* b_o   = (const float*)d_in[4];
    float* out = (float*)d_out;

    __half *xh, *w1h, *w2h, *qkv, *ah;
    float* b1;
    cudaGetSymbolAddress((void**)&xh, g_xh);
    cudaGetSymbolAddress((void**)&w1h, g_w1h); cudaGetSymbolAddress((void**)&w2h, g_w2h);
    cudaGetSymbolAddress((void**)&qkv, g_qkv); cudaGetSymbolAddress((void**)&ah, g_ah);
    cudaGetSymbolAddress((void**)&b1, g_b1);

    cudaFuncSetAttribute(mma_gemm, cudaFuncAttributeMaxDynamicSharedMemorySize, GEMM_SMEM);
    cudaFuncSetAttribute(attn_fa, cudaFuncAttributeMaxDynamicSharedMemorySize, ATTN_SMEM);

    // prep: round x; transpose weights (Q columns of w_qkv pre-scaled by 1/8);
    // bias with Q part pre-scaled.
    round_h8<<<(MM * CC / 8 + 255) / 256, 256>>>((const float4*)x, (uint4*)xh, MM * CC / 8);
    transpose_h<<<dim3(3 * CC / 32, CC / 32), dim3(32, 8)>>>(w_qkv, w1h, CC, 3 * CC, CC);
    transpose_h<<<dim3(CC / 32, CC / 32), dim3(32, 8)>>>(w_o, w2h, CC, CC, 0);
    scale_bias<<<(3 * CC + 255) / 256, 256>>>(b_qkv, b1, 3 * CC);

    // 1) QKV projection -> fp16 (Q pre-scaled)
    mma_gemm<<<dim3(3 * CC / 128, MM / 128), 256, GEMM_SMEM>>>(
        xh, w1h, b1, (float*)0, qkv, 3 * CC, CC);

    // 2) attention (two-pass flash, TQ=64, pair-processed, diagonal-only masking)
    size_t o_elems = (size_t)MM * CC;
    float* attw = ((size_t)out_size > o_elems) ? out + o_elems : (float*)0;
    dim3 g2(TT / 64, HH, BB);
    attn_fa<<<g2, 256, ATTN_SMEM>>>(qkv, attw, ah);

    // 3) output projection (fp32 out, streaming)
    mma_gemm<<<dim3(CC / 128, MM / 128), 256, GEMM_SMEM>>>(
        ah, w2h, b_o, out, (__half*)0, CC, CC);
}